// round 1
// baseline (speedup 1.0000x reference)
#include <cuda_runtime.h>
#include <cuda_bf16.h>

#define NUM_EXPERTS 16
#define TOP_K 2
#define Z_LOSS 1e-3f
#define ALPHA (1.0f / 1000.0f)

#define R_BLOCKS 2048
#define R_THREADS 256
// total elements = 4*4096*2048 = 33554432 floats = 8388608 float4
// 8388608 / (2048*256) = 16 float4 per thread exactly

__device__ float g_partials[R_BLOCKS];

__global__ __launch_bounds__(R_THREADS) void reduce_kernel(const float4* __restrict__ x) {
    __shared__ float sdata[R_THREADS];
    const int tid = threadIdx.x;
    const unsigned gid = blockIdx.x * R_THREADS + tid;
    const unsigned stride = R_BLOCKS * R_THREADS;

    float s0 = 0.f, s1 = 0.f, s2 = 0.f, s3 = 0.f;
#pragma unroll
    for (int i = 0; i < 16; i++) {
        float4 v = x[gid + (unsigned)i * stride];
        s0 += v.x; s1 += v.y; s2 += v.z; s3 += v.w;
    }
    float s = (s0 + s1) + (s2 + s3);

    // warp reduce
#pragma unroll
    for (int off = 16; off > 0; off >>= 1)
        s += __shfl_down_sync(0xffffffffu, s, off);

    if ((tid & 31) == 0) sdata[tid >> 5] = s;
    __syncthreads();
    if (tid < 32) {
        float v = (tid < R_THREADS / 32) ? sdata[tid] : 0.f;
#pragma unroll
        for (int off = 4; off > 0; off >>= 1)
            v += __shfl_down_sync(0xffffffffu, v, off);
        if (tid == 0) g_partials[blockIdx.x] = v;
    }
}

__global__ __launch_bounds__(256) void finalize_kernel(
    const float* __restrict__ prototypes,
    const float* __restrict__ usage_ema,
    float* __restrict__ out, int out_size, float inv_n)
{
    __shared__ double sdata[8];
    const int tid = threadIdx.x;

    // initialize every output element (d_out is poisoned with 0xAA)
    for (int i = tid; i < out_size; i += 256) out[i] = 0.0f;

    // reduce 2048 partials in double
    double s = 0.0;
#pragma unroll
    for (int i = 0; i < R_BLOCKS / 256; i++)
        s += (double)g_partials[tid + i * 256];
#pragma unroll
    for (int off = 16; off > 0; off >>= 1)
        s += __shfl_down_sync(0xffffffffu, s, off);
    if ((tid & 31) == 0) sdata[tid >> 5] = s;
    __syncthreads();

    if (tid == 0) {
        double tot = 0.0;
#pragma unroll
        for (int i = 0; i < 8; i++) tot = tot + sdata[i];
        float x = (float)(tot * (double)inv_n);

        // sim = -(p_e - x)^2 ; softmax
        float sim[NUM_EXPERTS];
        float mx = -3.4e38f;
        for (int e = 0; e < NUM_EXPERTS; e++) {
            float d = prototypes[e] - x;
            sim[e] = -d * d;
            if (sim[e] > mx) mx = sim[e];
        }
        float probs[NUM_EXPERTS];
        float denom = 0.f;
        for (int e = 0; e < NUM_EXPERTS; e++) {
            probs[e] = expf(sim[e] - mx);
            denom += probs[e];
        }
        float inv_denom = 1.0f / denom;
        for (int e = 0; e < NUM_EXPERTS; e++) probs[e] *= inv_denom;

        // stable top-2 (ties -> lowest index first, matching jax.lax.top_k)
        int i0 = 0;
        for (int e = 1; e < NUM_EXPERTS; e++)
            if (probs[e] > probs[i0]) i0 = e;
        int i1 = (i0 == 0) ? 1 : 0;
        for (int e = 0; e < NUM_EXPERTS; e++) {
            if (e == i0) continue;
            if (probs[e] > probs[i1]) i1 = e;
        }

        float mask[NUM_EXPERTS];
        for (int e = 0; e < NUM_EXPERTS; e++) mask[e] = 0.f;
        mask[i0] = 1.f; mask[i1] = 1.f;

        const float target = 1.0f / NUM_EXPERTS;
        float acc = 0.f;
        float ema[NUM_EXPERTS];
        for (int e = 0; e < NUM_EXPERTS; e++) {
            ema[e] = (1.0f - ALPHA) * usage_ema[e] + ALPHA * mask[e];
            float d = ema[e] - target;
            acc += d * d;
        }
        float balance_loss = (acc / NUM_EXPERTS) * Z_LOSS;

        // output layout: mask[16], probs[16], loss[1], ema[16], topk_idx[2]
        int o = 0;
        for (int e = 0; e < NUM_EXPERTS; e++) out[o++] = mask[e];
        for (int e = 0; e < NUM_EXPERTS; e++) out[o++] = probs[e];
        out[o++] = balance_loss;
        for (int e = 0; e < NUM_EXPERTS; e++) out[o++] = ema[e];
        out[o++] = (float)i0;
        out[o++] = (float)i1;
    }
}

extern "C" void kernel_launch(void* const* d_in, const int* in_sizes, int n_in,
                              void* d_out, int out_size) {
    const float* wm        = (const float*)d_in[0];
    const float* protos    = (const float*)d_in[1];
    const float* usage_ema = (const float*)d_in[2];
    float* out = (float*)d_out;

    const int n = in_sizes[0];  // 33554432
    reduce_kernel<<<R_BLOCKS, R_THREADS>>>((const float4*)wm);
    finalize_kernel<<<1, 256>>>(protos, usage_ema, out, out_size, 1.0f / (float)n);
}